// round 10
// baseline (speedup 1.0000x reference)
#include <cuda_runtime.h>
#include <cuda_fp16.h>
#include <cstdint>

// Problem constants
#define TOK   4096      // B*T
#define T_SEQ 2048
#define C_EMB 1024
#define NHEAD 16
#define HD    64
#define HID   2816

// ---------------- scratch (static device globals; no allocations) ----------
__device__ __align__(16) float g_qkv[(size_t)TOK * 3 * C_EMB];
__device__ __align__(16) float g_x2 [(size_t)TOK * C_EMB];
__device__ __align__(16) float g_fc1[(size_t)TOK * HID];
__device__ __align__(16) float g_fc2[(size_t)TOK * HID];
// fp16 activations (GEMM A operands)
__device__ __align__(16) __half g_h [(size_t)TOK * C_EMB];
__device__ __align__(16) __half g_y [(size_t)TOK * C_EMB];
__device__ __align__(16) __half g_m [(size_t)TOK * HID];
// transposed fp16 weights [N][K]
__device__ __align__(16) __half g_wqkvT[(size_t)3 * C_EMB * C_EMB];
__device__ __align__(16) __half g_wapT [(size_t)C_EMB * C_EMB];
__device__ __align__(16) __half g_wfc1T[(size_t)HID * C_EMB];
__device__ __align__(16) __half g_wfc2T[(size_t)HID * C_EMB];
__device__ __align__(16) __half g_wmpT [(size_t)C_EMB * HID];
// rope cos/sin table [T_SEQ][32]
__device__ __align__(16) float2 g_rope[(size_t)T_SEQ * 32];

// ---------------- helpers ---------------------------------------------------
__device__ __forceinline__ uint32_t f2tf(float f) {
    uint32_t u;
    asm("cvt.rna.tf32.f32 %0, %1;" : "=r"(u) : "f"(f));
    return u;
}

__device__ __forceinline__ void mma_tf32(float* d, const uint32_t* a,
                                         const uint32_t* b) {
    asm volatile(
        "mma.sync.aligned.m16n8k8.row.col.f32.tf32.tf32.f32 "
        "{%0,%1,%2,%3}, {%4,%5,%6,%7}, {%8,%9}, {%0,%1,%2,%3};\n"
        : "+f"(d[0]), "+f"(d[1]), "+f"(d[2]), "+f"(d[3])
        : "r"(a[0]), "r"(a[1]), "r"(a[2]), "r"(a[3]), "r"(b[0]), "r"(b[1]));
}

__device__ __forceinline__ void mma_f16(float* d, const uint32_t* a,
                                        const uint32_t* b) {
    asm volatile(
        "mma.sync.aligned.m16n8k16.row.col.f32.f16.f16.f32 "
        "{%0,%1,%2,%3}, {%4,%5,%6,%7}, {%8,%9}, {%0,%1,%2,%3};\n"
        : "+f"(d[0]), "+f"(d[1]), "+f"(d[2]), "+f"(d[3])
        : "r"(a[0]), "r"(a[1]), "r"(a[2]), "r"(a[3]), "r"(b[0]), "r"(b[1]));
}

__device__ __forceinline__ void cp_async16(void* smem, const void* gmem) {
    uint32_t s = (uint32_t)__cvta_generic_to_shared(smem);
    asm volatile("cp.async.ca.shared.global [%0], [%1], 16;\n"
                 :: "r"(s), "l"(gmem));
}

__device__ __forceinline__ uint32_t h2pack(float a, float b) {
    __half2 h = __floats2half2_rn(a, b);
    return *(uint32_t*)&h;
}

__device__ __forceinline__ void hsplit2(float a, float b,
                                        uint32_t& hi, uint32_t& lo) {
    __half ha = __float2half_rn(a), hb = __float2half_rn(b);
    __half la = __float2half_rn(a - __half2float(ha));
    __half lb = __float2half_rn(b - __half2float(hb));
    hi = (uint32_t)__half_as_ushort(ha) | ((uint32_t)__half_as_ushort(hb) << 16);
    lo = (uint32_t)__half_as_ushort(la) | ((uint32_t)__half_as_ushort(lb) << 16);
}

// ---------------- weight transpose + fp16 convert: W[K][N] -> T[N][K] -------
__global__ __launch_bounds__(256) void tconv_k(const float* __restrict__ W,
                                               __half* __restrict__ T,
                                               int K, int N) {
    __shared__ float t[32][33];
    int tx = threadIdx.x, ty = threadIdx.y;
    int tid = ty * 32 + tx;
    int n0 = blockIdx.x * 32, k0 = blockIdx.y * 32;
    #pragma unroll
    for (int i = 0; i < 4; i++) {
        int kk = ty * 4 + i;
        t[kk][tx] = W[(size_t)(k0 + kk) * N + n0 + tx];
    }
    __syncthreads();
    // packed writes: 512 uint32 per tile, 2 per thread
    #pragma unroll
    for (int i = 0; i < 2; i++) {
        int idx = tid + i * 256;
        int n = idx >> 4;
        int kp = idx & 15;
        uint32_t val = h2pack(t[2 * kp][n], t[2 * kp + 1][n]);
        *(uint32_t*)&T[(size_t)(n0 + n) * K + k0 + 2 * kp] = val;
    }
}

// ---------------- RMSNorm -> fp16 output ------------------------------------
__global__ __launch_bounds__(256) void rmsnorm_k(const float* __restrict__ x,
                                                 const float* __restrict__ sc,
                                                 __half* __restrict__ out) {
    int row = blockIdx.x;
    const float4* xr = (const float4*)(x + (size_t)row * C_EMB);
    float4 v = xr[threadIdx.x];
    float ss = v.x * v.x + v.y * v.y + v.z * v.z + v.w * v.w;
    #pragma unroll
    for (int o = 16; o; o >>= 1) ss += __shfl_xor_sync(0xffffffffu, ss, o);
    __shared__ float red[8];
    int wid = threadIdx.x >> 5, lane = threadIdx.x & 31;
    if (lane == 0) red[wid] = ss;
    __syncthreads();
    if (wid == 0) {
        float t = (lane < 8) ? red[lane] : 0.f;
        #pragma unroll
        for (int o = 4; o; o >>= 1) t += __shfl_xor_sync(0xffffffffu, t, o);
        if (lane == 0) red[0] = t;
    }
    __syncthreads();
    float inv = rsqrtf(red[0] * (1.0f / C_EMB) + 1e-5f);
    float4 s4 = ((const float4*)sc)[threadIdx.x];
    uint2 o4;
    o4.x = h2pack(v.x * inv * s4.x, v.y * inv * s4.y);
    o4.y = h2pack(v.z * inv * s4.z, v.w * inv * s4.w);
    ((uint2*)(out + (size_t)row * C_EMB))[threadIdx.x] = o4;
}

// ---------------- fp16 tensor-core GEMM, 3-stage cp.async pipeline ----------
#define HST 20   // 32-bit words per smem row (32 fp16 + 8 pad)
#define GEMM_SMEM (6 * 128 * HST * 4)   // 3 stages x (A+B) = 61440 B

__global__ __launch_bounds__(256) void h16gemm_k(const __half* __restrict__ A,
                                                 const __half* __restrict__ B,
                                                 float* __restrict__ C,
                                                 const float* __restrict__ R,
                                                 int M, int N, int K) {
    extern __shared__ uint32_t gsm[];
    uint32_t* As = gsm;                      // [3][128*HST]
    uint32_t* Bs = gsm + 3 * 128 * HST;      // [3][128*HST]

    int tid  = threadIdx.x;
    int wid  = tid >> 5;
    int lane = tid & 31;
    int g = lane >> 2;
    int q = lane & 3;
    int wm = (wid >> 2) * 64;
    int wn = (wid & 3) * 32;
    int bx = blockIdx.x * 128;
    int by = blockIdx.y * 128;

    int l_row = tid >> 2;
    int l_c   = tid & 3;

    const __half* Agp = A + (size_t)(by + l_row) * K + l_c * 8;
    const __half* Bgp = B + (size_t)(bx + l_row) * K + l_c * 8;

    float acc[4][4][4];
    #pragma unroll
    for (int i = 0; i < 4; i++)
        #pragma unroll
        for (int j = 0; j < 4; j++)
            #pragma unroll
            for (int e = 0; e < 4; e++) acc[i][j][e] = 0.f;

    auto load_stage = [&](int buf, int k0) {
        uint32_t* Ab = As + buf * 128 * HST;
        uint32_t* Bb = Bs + buf * 128 * HST;
        #pragma unroll
        for (int i = 0; i < 2; i++) {
            int row = l_row + i * 64;
            cp_async16(&Ab[row * HST + l_c * 4],
                       Agp + (size_t)i * 64 * K + k0);
            cp_async16(&Bb[row * HST + l_c * 4],
                       Bgp + (size_t)i * 64 * K + k0);
        }
        asm volatile("cp.async.commit_group;\n");
    };

    int KT = K >> 5;
    load_stage(0, 0);
    if (KT > 1) load_stage(1, 32);

    for (int kt = 0; kt < KT; kt++) {
        if (kt + 2 < KT) {
            asm volatile("cp.async.wait_group 1;\n");
        } else {
            asm volatile("cp.async.wait_group 0;\n");
        }
        __syncthreads();
        if (kt + 2 < KT) load_stage((kt + 2) % 3, (kt + 2) << 5);

        int buf = kt % 3;
        const uint32_t* Ab = As + buf * 128 * HST;
        const uint32_t* Bb = Bs + buf * 128 * HST;
        #pragma unroll
        for (int ks = 0; ks < 2; ks++) {
            uint32_t af[4][4], bf[4][2];
            #pragma unroll
            for (int mt = 0; mt < 4; mt++) {
                int base = (wm + 16 * mt + g) * HST + ks * 8 + q;
                af[mt][0] = Ab[base];
                af[mt][1] = Ab[base + 8 * HST];
                af[mt][2] = Ab[base + 4];
                af[mt][3] = Ab[base + 8 * HST + 4];
            }
            #pragma unroll
            for (int nt = 0; nt < 4; nt++) {
                int base = (wn + 8 * nt + g) * HST + ks * 8 + q;
                bf[nt][0] = Bb[base];
                bf[nt][1] = Bb[base + 4];
            }
            #pragma unroll
            for (int mt = 0; mt < 4; mt++)
                #pragma unroll
                for (int nt = 0; nt < 4; nt++)
                    mma_f16(acc[mt][nt], af[mt], bf[nt]);
        }
        __syncthreads();
    }

    #pragma unroll
    for (int mt = 0; mt < 4; mt++) {
        #pragma unroll
        for (int nt = 0; nt < 4; nt++) {
            int r0 = by + wm + 16 * mt + g;
            int c0 = bx + wn + 8 * nt + 2 * q;
            float2 v0 = make_float2(acc[mt][nt][0], acc[mt][nt][1]);
            float2 v1 = make_float2(acc[mt][nt][2], acc[mt][nt][3]);
            if (R) {
                float2 r0v = *(const float2*)(R + (size_t)r0 * N + c0);
                float2 r1v = *(const float2*)(R + (size_t)(r0 + 8) * N + c0);
                v0.x += r0v.x; v0.y += r0v.y;
                v1.x += r1v.x; v1.y += r1v.y;
            }
            *(float2*)(C + (size_t)r0 * N + c0) = v0;
            *(float2*)(C + (size_t)(r0 + 8) * N + c0) = v1;
        }
    }
}

// ---------------- rope table build ------------------------------------------
__global__ __launch_bounds__(256) void rope_tab_k(float2* __restrict__ tab) {
    int idx = blockIdx.x * 256 + threadIdx.x;   // 2048*32
    int t = idx >> 5;
    int p = idx & 31;
    float ang = (float)t * powf(10000.0f, -(float)p / 32.0f);
    tab[idx] = make_float2(cosf(ang), sinf(ang));
}

// ---------------- RoPE: table-based, float4 (2 pairs) per thread ------------
__global__ __launch_bounds__(256) void rope_k(float* __restrict__ qkv,
                                              const float2* __restrict__ tab) {
    int idx = blockIdx.x * 256 + threadIdx.x;   // 2^21 threads
    int j     = idx & 15;            // float4 within head (covers pairs 2j,2j+1)
    int h     = (idx >> 4) & 15;
    int which = (idx >> 8) & 1;      // 0 = q, 1 = k
    int tok   = idx >> 9;            // 0..4095
    int t     = tok & 2047;
    size_t off = (size_t)tok * 3072 + (size_t)which * 1024 + h * 64 + j * 4;
    float4 v = *(float4*)(qkv + off);
    float2 cs0 = tab[t * 32 + 2 * j];
    float2 cs1 = tab[t * 32 + 2 * j + 1];
    float4 o;
    o.x = v.x * cs0.x - v.y * cs0.y;
    o.y = v.x * cs0.y + v.y * cs0.x;
    o.z = v.z * cs1.x - v.w * cs1.y;
    o.w = v.z * cs1.y + v.w * cs1.x;
    *(float4*)(qkv + off) = o;
}

// ---------------- Flash attention: fp16 QK^T (2-term), tf32 PV --------------
#define QST 36
#define FST 68
#define VST 72
#define BQ 128
#define BK 64

__global__ __launch_bounds__(256, 2)
void flash_mma_k(const float* __restrict__ qkv,
                 const int* __restrict__ ymask,
                 __half* __restrict__ y) {
    extern __shared__ uint32_t dyn[];
    uint32_t* Qh = dyn;
    uint32_t* Ql = Qh + BQ * QST;
    uint32_t* Kh = Ql + BQ * QST;
    uint32_t* Kl = Kh + BK * QST;
    uint32_t* Ps = Kl + BK * QST;
    uint32_t* Vs = Ps + BQ * FST;
    __shared__ int yms[64];

    int tid = threadIdx.x;
    int w = tid >> 5, lane = tid & 31;
    int g = lane >> 2, q = lane & 3;
    int qt = gridDim.x - 1 - blockIdx.x;
    int h = blockIdx.y, b = blockIdx.z;
    int q0 = qt * BQ;
    const float* base = qkv + (size_t)(b * T_SEQ) * 3072 + h * 64;

    #pragma unroll
    for (int i = 0; i < 8; i++) {
        int e = tid + i * 256;
        int r = e >> 4;
        int c = (e & 15) * 4;
        float4 v = *(const float4*)(base + (size_t)(q0 + r) * 3072 + c);
        uint2 hv, lv;
        hsplit2(v.x, v.y, hv.x, lv.x);
        hsplit2(v.z, v.w, hv.y, lv.y);
        int o = r * QST + (c >> 1);
        *(uint2*)&Qh[o] = hv;
        *(uint2*)&Ql[o] = lv;
    }
    if (tid < 64) yms[tid] = ymask[b * 64 + tid];
    __syncthreads();

    int wr = w * 16;
    float o_acc[8][4];
    #pragma unroll
    for (int nt = 0; nt < 8; nt++)
        #pragma unroll
        for (int e = 0; e < 4; e++) o_acc[nt][e] = 0.f;
    float m0 = -1e30f, m1 = -1e30f, l0 = 0.f, l1 = 0.f;

    int rg0 = q0 + wr + g, rg1 = rg0 + 8;
    int nkt = 2 * qt + 2;

    for (int kt = 0; kt < nkt; kt++) {
        int k0 = kt * BK;
        #pragma unroll
        for (int i = 0; i < 4; i++) {
            int e = tid + i * 256;
            int r = e >> 4;
            int c = (e & 15) * 4;
            const float* gsrc = base + (size_t)(k0 + r) * 3072 + c;
            float4 kv4 = *(const float4*)(gsrc + 1024);
            float4 vv4 = *(const float4*)(gsrc + 2048);
            uint2 hv, lv;
            hsplit2(kv4.x, kv4.y, hv.x, lv.x);
            hsplit2(kv4.z, kv4.w, hv.y, lv.y);
            int ok = r * QST + (c >> 1);
            *(uint2*)&Kh[ok] = hv;
            *(uint2*)&Kl[ok] = lv;
            int ov = r * VST + c;
            Vs[ov]     = f2tf(vv4.x);
            Vs[ov + 1] = f2tf(vv4.y);
            Vs[ov + 2] = f2tf(vv4.z);
            Vs[ov + 3] = f2tf(vv4.w);
        }
        __syncthreads();

        bool active = (k0 <= q0 + wr + 15);
        if (active) {
            float s[8][4];
            #pragma unroll
            for (int nt = 0; nt < 8; nt++)
                #pragma unroll
                for (int e = 0; e < 4; e++) s[nt][e] = 0.f;

            #pragma unroll
            for (int ks = 0; ks < 4; ks++) {
                int ac = ks * 8 + q;
                uint32_t ah[4], al[4];
                ah[0] = Qh[(wr + g) * QST + ac];
                ah[1] = Qh[(wr + g + 8) * QST + ac];
                ah[2] = Qh[(wr + g) * QST + ac + 4];
                ah[3] = Qh[(wr + g + 8) * QST + ac + 4];
                al[0] = Ql[(wr + g) * QST + ac];
                al[1] = Ql[(wr + g + 8) * QST + ac];
                al[2] = Ql[(wr + g) * QST + ac + 4];
                al[3] = Ql[(wr + g + 8) * QST + ac + 4];
                #pragma unroll
                for (int nt = 0; nt < 8; nt++) {
                    int br = (nt * 8 + g) * QST + ac;
                    uint32_t bh[2] = {Kh[br], Kh[br + 4]};
                    uint32_t bl[2] = {Kl[br], Kl[br + 4]};
                    mma_f16(s[nt], ah, bh);
                    mma_f16(s[nt], al, bh);
                    mma_f16(s[nt], ah, bl);
                }
            }

            bool needmask = (k0 + BK - 1 > q0 + wr);
            bool istext = (q0 == 0) && (k0 == 0);
            float rm0 = -1e30f, rm1 = -1e30f;
            #pragma unroll
            for (int nt = 0; nt < 8; nt++) {
                #pragma unroll
                for (int e = 0; e < 4; e++) {
                    float sv = s[nt][e] * 0.125f;
                    if (needmask) {
                        int row = (e >= 2) ? rg1 : rg0;
                        int kg = k0 + nt * 8 + 2 * q + (e & 1);
                        bool ok = (kg <= row);
                        if (istext)
                            ok = ok || (row < 64 && kg < 64 && yms[row] && yms[kg]);
                        sv = ok ? sv : -1e30f;
                    }
                    s[nt][e] = sv;
                    if (e < 2) rm0 = fmaxf(rm0, sv);
                    else       rm1 = fmaxf(rm1, sv);
                }
            }
            rm0 = fmaxf(rm0, __shfl_xor_sync(0xffffffffu, rm0, 1));
            rm0 = fmaxf(rm0, __shfl_xor_sync(0xffffffffu, rm0, 2));
            rm1 = fmaxf(rm1, __shfl_xor_sync(0xffffffffu, rm1, 1));
            rm1 = fmaxf(rm1, __shfl_xor_sync(0xffffffffu, rm1, 2));

            float mn0 = fmaxf(m0, rm0), mn1 = fmaxf(m1, rm1);
            float a0 = __expf(m0 - mn0), a1 = __expf(m1 - mn1);
            float rl0 = 0.f, rl1 = 0.f;
            #pragma unroll
            for (int nt = 0; nt < 8; nt++) {
                float p0 = __expf(s[nt][0] - mn0);
                float p1 = __expf(s[nt][1] - mn0);
                float p2 = __expf(s[nt][2] - mn1);
                float p3 = __expf(s[nt][3] - mn1);
                rl0 += p0 + p1;
                rl1 += p2 + p3;
                int pc = nt * 8 + 2 * q;
                *(uint2*)&Ps[(wr + g) * FST + pc]     = make_uint2(f2tf(p0), f2tf(p1));
                *(uint2*)&Ps[(wr + g + 8) * FST + pc] = make_uint2(f2tf(p2), f2tf(p3));
                o_acc[nt][0] *= a0; o_acc[nt][1] *= a0;
                o_acc[nt][2] *= a1; o_acc[nt][3] *= a1;
            }
            rl0 += __shfl_xor_sync(0xffffffffu, rl0, 1);
            rl0 += __shfl_xor_sync(0xffffffffu, rl0, 2);
            rl1 += __shfl_xor_sync(0xffffffffu, rl1, 1);
            rl1 += __shfl_xor_sync(0xffffffffu, rl1, 2);
            l0 = l0 * a0 + rl0;
            l1 = l1 * a1 + rl1;
            m0 = mn0; m1 = mn1;

            __syncwarp();

            #pragma unroll
            for (int ks = 0; ks < 8; ks++) {
                int pc = ks * 8 + q;
                uint32_t a[4];
                a[0] = Ps[(wr + g) * FST + pc];
                a[1] = Ps[(wr + g + 8) * FST + pc];
                a[2] = Ps[(wr + g) * FST + pc + 4];
                a[3] = Ps[(wr + g + 8) * FST + pc + 4];
                #pragma unroll
                for (int nt = 0; nt < 8; nt++) {
                    uint32_t bv[2];
                    bv[0] = Vs[(ks * 8 + q) * VST + nt * 8 + g];
                    bv[1] = Vs[(ks * 8 + q + 4) * VST + nt * 8 + g];
                    mma_tf32(o_acc[nt], a, bv);
                }
            }
        }
        __syncthreads();
    }

    float inv0 = 1.f / l0, inv1 = 1.f / l1;
    __half* yp0 = y + (size_t)(b * T_SEQ + rg0) * 1024 + h * 64;
    __half* yp1 = yp0 + (size_t)8 * 1024;
    #pragma unroll
    for (int nt = 0; nt < 8; nt++) {
        int c = nt * 8 + 2 * q;
        *(uint32_t*)(yp0 + c) = h2pack(o_acc[nt][0] * inv0, o_acc[nt][1] * inv0);
        *(uint32_t*)(yp1 + c) = h2pack(o_acc[nt][2] * inv1, o_acc[nt][3] * inv1);
    }
}

// ---------------- SiLU(a) * b -> fp16 ---------------------------------------
__global__ __launch_bounds__(256) void silu_mul_k(const float* __restrict__ a,
                                                  const float* __restrict__ b,
                                                  __half* __restrict__ m,
                                                  int n4) {
    int i = blockIdx.x * 256 + threadIdx.x;
    if (i >= n4) return;
    float4 av = ((const float4*)a)[i];
    float4 bv = ((const float4*)b)[i];
    float o0 = av.x * bv.x / (1.f + __expf(-av.x));
    float o1 = av.y * bv.y / (1.f + __expf(-av.y));
    float o2 = av.z * bv.z / (1.f + __expf(-av.z));
    float o3 = av.w * bv.w / (1.f + __expf(-av.w));
    uint2 o;
    o.x = h2pack(o0, o1);
    o.y = h2pack(o2, o3);
    ((uint2*)m)[i] = o;
}

// ---------------- launch ----------------------------------------------------
#define FLASH_SMEM ((2 * BQ * QST + 2 * BK * QST + BQ * FST + BK * VST) * 4)

extern "C" void kernel_launch(void* const* d_in, const int* in_sizes, int n_in,
                              void* d_out, int out_size) {
    const float* x    = (const float*)d_in[0];
    const int*   ym   = (const int*)  d_in[1];
    const float* Wqkv = (const float*)d_in[2];
    const float* Wap  = (const float*)d_in[3];
    const float* sc1  = (const float*)d_in[4];
    const float* sc2  = (const float*)d_in[5];
    const float* Wfc1 = (const float*)d_in[6];
    const float* Wfc2 = (const float*)d_in[7];
    const float* Wmp  = (const float*)d_in[8];
    float* out = (float*)d_out;

    float *qkv, *x2, *fc1, *fc2;
    float2* ropet;
    __half *h, *y, *m, *wqkvT, *wapT, *wfc1T, *wfc2T, *wmpT;
    cudaGetSymbolAddress((void**)&qkv,   g_qkv);
    cudaGetSymbolAddress((void**)&x2,    g_x2);
    cudaGetSymbolAddress((void**)&fc1,   g_fc1);
    cudaGetSymbolAddress((void**)&fc2,   g_fc2);
    cudaGetSymbolAddress((void**)&h,     g_h);
    cudaGetSymbolAddress((void**)&y,     g_y);
    cudaGetSymbolAddress((void**)&m,     g_m);
    cudaGetSymbolAddress((void**)&wqkvT, g_wqkvT);
    cudaGetSymbolAddress((void**)&wapT,  g_wapT);
    cudaGetSymbolAddress((void**)&wfc1T, g_wfc1T);
    cudaGetSymbolAddress((void**)&wfc2T, g_wfc2T);
    cudaGetSymbolAddress((void**)&wmpT,  g_wmpT);
    cudaGetSymbolAddress((void**)&ropet, g_rope);

    cudaFuncSetAttribute(flash_mma_k,
                         cudaFuncAttributeMaxDynamicSharedMemorySize,
                         FLASH_SMEM);
    cudaFuncSetAttribute(h16gemm_k,
                         cudaFuncAttributeMaxDynamicSharedMemorySize,
                         GEMM_SMEM);

    dim3 tb(32, 8);
    // 0) weight transpose + fp16 convert; rope table
    tconv_k<<<dim3(3072 / 32, 1024 / 32), tb>>>(Wqkv, wqkvT, C_EMB, 3072);
    tconv_k<<<dim3(1024 / 32, 1024 / 32), tb>>>(Wap, wapT, C_EMB, C_EMB);
    tconv_k<<<dim3(2816 / 32, 1024 / 32), tb>>>(Wfc1, wfc1T, C_EMB, HID);
    tconv_k<<<dim3(2816 / 32, 1024 / 32), tb>>>(Wfc2, wfc2T, C_EMB, HID);
    tconv_k<<<dim3(1024 / 32, 2816 / 32), tb>>>(Wmp, wmpT, HID, C_EMB);
    rope_tab_k<<<(T_SEQ * 32) / 256, 256>>>(ropet);

    // 1) h = fp16(rmsnorm(x, scale1))
    rmsnorm_k<<<TOK, 256>>>(x, sc1, h);
    // 2) qkv = h @ Wqkv
    h16gemm_k<<<dim3(3072 / 128, TOK / 128), 256, GEMM_SMEM>>>(
        h, wqkvT, qkv, nullptr, TOK, 3072, C_EMB);
    // 3) RoPE in place (table-based)
    rope_k<<<(1 << 21) / 256, 256>>>(qkv, ropet);
    // 4) attention -> y (fp16)
    flash_mma_k<<<dim3(T_SEQ / BQ, NHEAD, 2), 256, FLASH_SMEM>>>(qkv, ym, y);
    // 5) x2 = x + y @ Wattn_proj
    h16gemm_k<<<dim3(C_EMB / 128, TOK / 128), 256, GEMM_SMEM>>>(
        y, wapT, x2, x, TOK, C_EMB, C_EMB);
    // 6) h = fp16(rmsnorm(x2, scale2))
    rmsnorm_k<<<TOK, 256>>>(x2, sc2, h);
    // 7) fc1 = h @ Wfc1 ; fc2 = h @ Wfc2
    h16gemm_k<<<dim3(HID / 128, TOK / 128), 256, GEMM_SMEM>>>(
        h, wfc1T, fc1, nullptr, TOK, HID, C_EMB);
    h16gemm_k<<<dim3(HID / 128, TOK / 128), 256, GEMM_SMEM>>>(
        h, wfc2T, fc2, nullptr, TOK, HID, C_EMB);
    // 8) m = fp16(silu(fc1) * fc2)
    int n4 = TOK * HID / 4;
    silu_mul_k<<<(n4 + 255) / 256, 256>>>(fc1, fc2, m, n4);
    // 9) out = x2 + m @ Wmlp_proj
    h16gemm_k<<<dim3(C_EMB / 128, TOK / 128), 256, GEMM_SMEM>>>(
        m, wmpT, out, x2, TOK, C_EMB, HID);
}

// round 12
// speedup vs baseline: 1.5598x; 1.5598x over previous
#include <cuda_runtime.h>
#include <cuda_fp16.h>
#include <cstdint>

// Problem constants
#define TOK   4096      // B*T
#define T_SEQ 2048
#define C_EMB 1024
#define NHEAD 16
#define HD    64
#define HID   2816

// ---------------- scratch (static device globals; no allocations) ----------
__device__ __align__(16) float g_qkv[(size_t)TOK * 3 * C_EMB];
__device__ __align__(16) float g_x2 [(size_t)TOK * C_EMB];
__device__ __align__(16) float g_fc1[(size_t)TOK * HID];
__device__ __align__(16) float g_fc2[(size_t)TOK * HID];   // unused in gate mode
// fp16 activations (GEMM A operands)
__device__ __align__(16) __half g_h [(size_t)TOK * C_EMB];
__device__ __align__(16) __half g_y [(size_t)TOK * C_EMB];
__device__ __align__(16) __half g_m [(size_t)TOK * HID];
// transposed fp16 weights [N][K]
__device__ __align__(16) __half g_wqkvT[(size_t)3 * C_EMB * C_EMB];
__device__ __align__(16) __half g_wapT [(size_t)C_EMB * C_EMB];
__device__ __align__(16) __half g_wfc1T[(size_t)HID * C_EMB];
__device__ __align__(16) __half g_wfc2T[(size_t)HID * C_EMB];
__device__ __align__(16) __half g_wmpT [(size_t)C_EMB * HID];
// rope cos/sin table [T_SEQ][32]
__device__ __align__(16) float2 g_rope[(size_t)T_SEQ * 32];

// ---------------- helpers ---------------------------------------------------
__device__ __forceinline__ uint32_t f2tf(float f) {
    uint32_t u;
    asm("cvt.rna.tf32.f32 %0, %1;" : "=r"(u) : "f"(f));
    return u;
}

__device__ __forceinline__ void mma_tf32(float* d, const uint32_t* a,
                                         const uint32_t* b) {
    asm volatile(
        "mma.sync.aligned.m16n8k8.row.col.f32.tf32.tf32.f32 "
        "{%0,%1,%2,%3}, {%4,%5,%6,%7}, {%8,%9}, {%0,%1,%2,%3};\n"
        : "+f"(d[0]), "+f"(d[1]), "+f"(d[2]), "+f"(d[3])
        : "r"(a[0]), "r"(a[1]), "r"(a[2]), "r"(a[3]), "r"(b[0]), "r"(b[1]));
}

__device__ __forceinline__ void mma_f16(float* d, const uint32_t* a,
                                        const uint32_t* b) {
    asm volatile(
        "mma.sync.aligned.m16n8k16.row.col.f32.f16.f16.f32 "
        "{%0,%1,%2,%3}, {%4,%5,%6,%7}, {%8,%9}, {%0,%1,%2,%3};\n"
        : "+f"(d[0]), "+f"(d[1]), "+f"(d[2]), "+f"(d[3])
        : "r"(a[0]), "r"(a[1]), "r"(a[2]), "r"(a[3]), "r"(b[0]), "r"(b[1]));
}

__device__ __forceinline__ void cp_async16(void* smem, const void* gmem) {
    uint32_t s = (uint32_t)__cvta_generic_to_shared(smem);
    asm volatile("cp.async.ca.shared.global [%0], [%1], 16;\n"
                 :: "r"(s), "l"(gmem));
}

__device__ __forceinline__ uint32_t h2pack(float a, float b) {
    __half2 h = __floats2half2_rn(a, b);
    return *(uint32_t*)&h;
}

__device__ __forceinline__ void hsplit2(float a, float b,
                                        uint32_t& hi, uint32_t& lo) {
    __half ha = __float2half_rn(a), hb = __float2half_rn(b);
    __half la = __float2half_rn(a - __half2float(ha));
    __half lb = __float2half_rn(b - __half2float(hb));
    hi = (uint32_t)__half_as_ushort(ha) | ((uint32_t)__half_as_ushort(hb) << 16);
    lo = (uint32_t)__half_as_ushort(la) | ((uint32_t)__half_as_ushort(lb) << 16);
}

// ---------------- weight transpose + fp16 convert (R9 version) --------------
__global__ __launch_bounds__(256) void tconv_k(const float* __restrict__ W,
                                               __half* __restrict__ T,
                                               int K, int N) {
    __shared__ float t[32][33];
    int tx = threadIdx.x, ty = threadIdx.y;
    int n0 = blockIdx.x * 32, k0 = blockIdx.y * 32;
    #pragma unroll
    for (int i = 0; i < 4; i++) {
        int kk = ty * 4 + i;
        t[kk][tx] = W[(size_t)(k0 + kk) * N + n0 + tx];
    }
    __syncthreads();
    #pragma unroll
    for (int i = 0; i < 4; i++) {
        int nn = ty * 4 + i;
        T[(size_t)(n0 + nn) * K + k0 + tx] = __float2half(t[tx][nn]);
    }
}

// ---------------- RMSNorm -> fp16 output ------------------------------------
__global__ __launch_bounds__(256) void rmsnorm_k(const float* __restrict__ x,
                                                 const float* __restrict__ sc,
                                                 __half* __restrict__ out) {
    int row = blockIdx.x;
    const float4* xr = (const float4*)(x + (size_t)row * C_EMB);
    float4 v = xr[threadIdx.x];
    float ss = v.x * v.x + v.y * v.y + v.z * v.z + v.w * v.w;
    #pragma unroll
    for (int o = 16; o; o >>= 1) ss += __shfl_xor_sync(0xffffffffu, ss, o);
    __shared__ float red[8];
    int wid = threadIdx.x >> 5, lane = threadIdx.x & 31;
    if (lane == 0) red[wid] = ss;
    __syncthreads();
    if (wid == 0) {
        float t = (lane < 8) ? red[lane] : 0.f;
        #pragma unroll
        for (int o = 4; o; o >>= 1) t += __shfl_xor_sync(0xffffffffu, t, o);
        if (lane == 0) red[0] = t;
    }
    __syncthreads();
    float inv = rsqrtf(red[0] * (1.0f / C_EMB) + 1e-5f);
    float4 s4 = ((const float4*)sc)[threadIdx.x];
    uint2 o4;
    o4.x = h2pack(v.x * inv * s4.x, v.y * inv * s4.y);
    o4.y = h2pack(v.z * inv * s4.z, v.w * inv * s4.w);
    ((uint2*)(out + (size_t)row * C_EMB))[threadIdx.x] = o4;
}

// ---------------- fp16 tensor-core GEMM (R9 2-stage, + gated epilogue) ------
// C[M,N] = A[M,K] @ B[N,K]^T (+R).
// If gate != nullptr: writes hout = fp16(silu(gate) * acc) instead of C.
#define HST 20   // 32-bit words per smem row (32 fp16 + 8 pad)

__global__ __launch_bounds__(256) void h16gemm_k(const __half* __restrict__ A,
                                                 const __half* __restrict__ B,
                                                 float* __restrict__ C,
                                                 const float* __restrict__ R,
                                                 const float* __restrict__ gate,
                                                 __half* __restrict__ hout,
                                                 int M, int N, int K) {
    __shared__ uint32_t As[2][128 * HST];
    __shared__ uint32_t Bs[2][128 * HST];

    int tid  = threadIdx.x;
    int wid  = tid >> 5;
    int lane = tid & 31;
    int g = lane >> 2;
    int q = lane & 3;
    int wm = (wid >> 2) * 64;
    int wn = (wid & 3) * 32;
    int bx = blockIdx.x * 128;
    int by = blockIdx.y * 128;

    int l_row = tid >> 2;
    int l_c   = tid & 3;

    const __half* Agp = A + (size_t)(by + l_row) * K + l_c * 8;
    const __half* Bgp = B + (size_t)(bx + l_row) * K + l_c * 8;

    float acc[4][4][4];
    #pragma unroll
    for (int i = 0; i < 4; i++)
        #pragma unroll
        for (int j = 0; j < 4; j++)
            #pragma unroll
            for (int e = 0; e < 4; e++) acc[i][j][e] = 0.f;

    auto load_stage = [&](int buf, int k0) {
        #pragma unroll
        for (int i = 0; i < 2; i++) {
            int row = l_row + i * 64;
            cp_async16(&As[buf][row * HST + l_c * 4],
                       Agp + (size_t)i * 64 * K + k0);
            cp_async16(&Bs[buf][row * HST + l_c * 4],
                       Bgp + (size_t)i * 64 * K + k0);
        }
        asm volatile("cp.async.commit_group;\n");
    };

    load_stage(0, 0);
    asm volatile("cp.async.wait_group 0;\n");
    __syncthreads();

    int KT = K >> 5;
    for (int kt = 0; kt < KT; kt++) {
        int buf = kt & 1;
        if (kt + 1 < KT) load_stage(buf ^ 1, (kt + 1) << 5);

        #pragma unroll
        for (int ks = 0; ks < 2; ks++) {
            uint32_t af[4][4], bf[4][2];
            #pragma unroll
            for (int mt = 0; mt < 4; mt++) {
                int base = (wm + 16 * mt + g) * HST + ks * 8 + q;
                af[mt][0] = As[buf][base];
                af[mt][1] = As[buf][base + 8 * HST];
                af[mt][2] = As[buf][base + 4];
                af[mt][3] = As[buf][base + 8 * HST + 4];
            }
            #pragma unroll
            for (int nt = 0; nt < 4; nt++) {
                int base = (wn + 8 * nt + g) * HST + ks * 8 + q;
                bf[nt][0] = Bs[buf][base];
                bf[nt][1] = Bs[buf][base + 4];
            }
            #pragma unroll
            for (int mt = 0; mt < 4; mt++)
                #pragma unroll
                for (int nt = 0; nt < 4; nt++)
                    mma_f16(acc[mt][nt], af[mt], bf[nt]);
        }

        asm volatile("cp.async.wait_group 0;\n");
        __syncthreads();
    }

    if (gate) {
        // m = fp16(silu(gate) * acc); matches silu_mul_k expression exactly
        #pragma unroll
        for (int mt = 0; mt < 4; mt++) {
            #pragma unroll
            for (int nt = 0; nt < 4; nt++) {
                int r0 = by + wm + 16 * mt + g;
                int c0 = bx + wn + 8 * nt + 2 * q;
                float2 g0 = *(const float2*)(gate + (size_t)r0 * N + c0);
                float2 g1 = *(const float2*)(gate + (size_t)(r0 + 8) * N + c0);
                float v00 = g0.x * acc[mt][nt][0] / (1.f + __expf(-g0.x));
                float v01 = g0.y * acc[mt][nt][1] / (1.f + __expf(-g0.y));
                float v10 = g1.x * acc[mt][nt][2] / (1.f + __expf(-g1.x));
                float v11 = g1.y * acc[mt][nt][3] / (1.f + __expf(-g1.y));
                *(uint32_t*)(hout + (size_t)r0 * N + c0)       = h2pack(v00, v01);
                *(uint32_t*)(hout + (size_t)(r0 + 8) * N + c0) = h2pack(v10, v11);
            }
        }
        return;
    }

    #pragma unroll
    for (int mt = 0; mt < 4; mt++) {
        #pragma unroll
        for (int nt = 0; nt < 4; nt++) {
            int r0 = by + wm + 16 * mt + g;
            int c0 = bx + wn + 8 * nt + 2 * q;
            float2 v0 = make_float2(acc[mt][nt][0], acc[mt][nt][1]);
            float2 v1 = make_float2(acc[mt][nt][2], acc[mt][nt][3]);
            if (R) {
                float2 r0v = *(const float2*)(R + (size_t)r0 * N + c0);
                float2 r1v = *(const float2*)(R + (size_t)(r0 + 8) * N + c0);
                v0.x += r0v.x; v0.y += r0v.y;
                v1.x += r1v.x; v1.y += r1v.y;
            }
            *(float2*)(C + (size_t)r0 * N + c0) = v0;
            *(float2*)(C + (size_t)(r0 + 8) * N + c0) = v1;
        }
    }
}

// ---------------- rope table build ------------------------------------------
__global__ __launch_bounds__(256) void rope_tab_k(float2* __restrict__ tab) {
    int idx = blockIdx.x * 256 + threadIdx.x;   // 2048*32
    int t = idx >> 5;
    int p = idx & 31;
    float ang = (float)t * powf(10000.0f, -(float)p / 32.0f);
    tab[idx] = make_float2(cosf(ang), sinf(ang));
}

// ---------------- RoPE: table-based, float4 (2 pairs) per thread ------------
__global__ __launch_bounds__(256) void rope_k(float* __restrict__ qkv,
                                              const float2* __restrict__ tab) {
    int idx = blockIdx.x * 256 + threadIdx.x;   // 2^21 threads
    int j     = idx & 15;
    int h     = (idx >> 4) & 15;
    int which = (idx >> 8) & 1;
    int tok   = idx >> 9;
    int t     = tok & 2047;
    size_t off = (size_t)tok * 3072 + (size_t)which * 1024 + h * 64 + j * 4;
    float4 v = *(float4*)(qkv + off);
    float2 cs0 = tab[t * 32 + 2 * j];
    float2 cs1 = tab[t * 32 + 2 * j + 1];
    float4 o;
    o.x = v.x * cs0.x - v.y * cs0.y;
    o.y = v.x * cs0.y + v.y * cs0.x;
    o.z = v.z * cs1.x - v.w * cs1.y;
    o.w = v.z * cs1.y + v.w * cs1.x;
    *(float4*)(qkv + off) = o;
}

// ---------------- Flash attention: fp16 QK^T (2-term), tf32 PV --------------
#define QST 36
#define FST 68
#define VST 72
#define BQ 128
#define BK 64

__global__ __launch_bounds__(256, 2)
void flash_mma_k(const float* __restrict__ qkv,
                 const int* __restrict__ ymask,
                 __half* __restrict__ y) {
    extern __shared__ uint32_t dyn[];
    uint32_t* Qh = dyn;
    uint32_t* Ql = Qh + BQ * QST;
    uint32_t* Kh = Ql + BQ * QST;
    uint32_t* Kl = Kh + BK * QST;
    uint32_t* Ps = Kl + BK * QST;
    uint32_t* Vs = Ps + BQ * FST;
    __shared__ int yms[64];

    int tid = threadIdx.x;
    int w = tid >> 5, lane = tid & 31;
    int g = lane >> 2, q = lane & 3;
    int qt = gridDim.x - 1 - blockIdx.x;
    int h = blockIdx.y, b = blockIdx.z;
    int q0 = qt * BQ;
    const float* base = qkv + (size_t)(b * T_SEQ) * 3072 + h * 64;

    #pragma unroll
    for (int i = 0; i < 8; i++) {
        int e = tid + i * 256;
        int r = e >> 4;
        int c = (e & 15) * 4;
        float4 v = *(const float4*)(base + (size_t)(q0 + r) * 3072 + c);
        uint2 hv, lv;
        hsplit2(v.x, v.y, hv.x, lv.x);
        hsplit2(v.z, v.w, hv.y, lv.y);
        int o = r * QST + (c >> 1);
        *(uint2*)&Qh[o] = hv;
        *(uint2*)&Ql[o] = lv;
    }
    if (tid < 64) yms[tid] = ymask[b * 64 + tid];
    __syncthreads();

    int wr = w * 16;
    float o_acc[8][4];
    #pragma unroll
    for (int nt = 0; nt < 8; nt++)
        #pragma unroll
        for (int e = 0; e < 4; e++) o_acc[nt][e] = 0.f;
    float m0 = -1e30f, m1 = -1e30f, l0 = 0.f, l1 = 0.f;

    int rg0 = q0 + wr + g, rg1 = rg0 + 8;
    int nkt = 2 * qt + 2;

    for (int kt = 0; kt < nkt; kt++) {
        int k0 = kt * BK;
        #pragma unroll
        for (int i = 0; i < 4; i++) {
            int e = tid + i * 256;
            int r = e >> 4;
            int c = (e & 15) * 4;
            const float* gsrc = base + (size_t)(k0 + r) * 3072 + c;
            float4 kv4 = *(const float4*)(gsrc + 1024);
            float4 vv4 = *(const float4*)(gsrc + 2048);
            uint2 hv, lv;
            hsplit2(kv4.x, kv4.y, hv.x, lv.x);
            hsplit2(kv4.z, kv4.w, hv.y, lv.y);
            int ok = r * QST + (c >> 1);
            *(uint2*)&Kh[ok] = hv;
            *(uint2*)&Kl[ok] = lv;
            int ov = r * VST + c;
            Vs[ov]     = f2tf(vv4.x);
            Vs[ov + 1] = f2tf(vv4.y);
            Vs[ov + 2] = f2tf(vv4.z);
            Vs[ov + 3] = f2tf(vv4.w);
        }
        __syncthreads();

        bool active = (k0 <= q0 + wr + 15);
        if (active) {
            float s[8][4];
            #pragma unroll
            for (int nt = 0; nt < 8; nt++)
                #pragma unroll
                for (int e = 0; e < 4; e++) s[nt][e] = 0.f;

            #pragma unroll
            for (int ks = 0; ks < 4; ks++) {
                int ac = ks * 8 + q;
                uint32_t ah[4], al[4];
                ah[0] = Qh[(wr + g) * QST + ac];
                ah[1] = Qh[(wr + g + 8) * QST + ac];
                ah[2] = Qh[(wr + g) * QST + ac + 4];
                ah[3] = Qh[(wr + g + 8) * QST + ac + 4];
                al[0] = Ql[(wr + g) * QST + ac];
                al[1] = Ql[(wr + g + 8) * QST + ac];
                al[2] = Ql[(wr + g) * QST + ac + 4];
                al[3] = Ql[(wr + g + 8) * QST + ac + 4];
                #pragma unroll
                for (int nt = 0; nt < 8; nt++) {
                    int br = (nt * 8 + g) * QST + ac;
                    uint32_t bh[2] = {Kh[br], Kh[br + 4]};
                    uint32_t bl[2] = {Kl[br], Kl[br + 4]};
                    mma_f16(s[nt], ah, bh);
                    mma_f16(s[nt], al, bh);
                    mma_f16(s[nt], ah, bl);
                }
            }

            bool needmask = (k0 + BK - 1 > q0 + wr);
            bool istext = (q0 == 0) && (k0 == 0);
            float rm0 = -1e30f, rm1 = -1e30f;
            #pragma unroll
            for (int nt = 0; nt < 8; nt++) {
                #pragma unroll
                for (int e = 0; e < 4; e++) {
                    float sv = s[nt][e] * 0.125f;
                    if (needmask) {
                        int row = (e >= 2) ? rg1 : rg0;
                        int kg = k0 + nt * 8 + 2 * q + (e & 1);
                        bool ok = (kg <= row);
                        if (istext)
                            ok = ok || (row < 64 && kg < 64 && yms[row] && yms[kg]);
                        sv = ok ? sv : -1e30f;
                    }
                    s[nt][e] = sv;
                    if (e < 2) rm0 = fmaxf(rm0, sv);
                    else       rm1 = fmaxf(rm1, sv);
                }
            }
            rm0 = fmaxf(rm0, __shfl_xor_sync(0xffffffffu, rm0, 1));
            rm0 = fmaxf(rm0, __shfl_xor_sync(0xffffffffu, rm0, 2));
            rm1 = fmaxf(rm1, __shfl_xor_sync(0xffffffffu, rm1, 1));
            rm1 = fmaxf(rm1, __shfl_xor_sync(0xffffffffu, rm1, 2));

            float mn0 = fmaxf(m0, rm0), mn1 = fmaxf(m1, rm1);
            float a0 = __expf(m0 - mn0), a1 = __expf(m1 - mn1);
            float rl0 = 0.f, rl1 = 0.f;
            #pragma unroll
            for (int nt = 0; nt < 8; nt++) {
                float p0 = __expf(s[nt][0] - mn0);
                float p1 = __expf(s[nt][1] - mn0);
                float p2 = __expf(s[nt][2] - mn1);
                float p3 = __expf(s[nt][3] - mn1);
                rl0 += p0 + p1;
                rl1 += p2 + p3;
                int pc = nt * 8 + 2 * q;
                *(uint2*)&Ps[(wr + g) * FST + pc]     = make_uint2(f2tf(p0), f2tf(p1));
                *(uint2*)&Ps[(wr + g + 8) * FST + pc] = make_uint2(f2tf(p2), f2tf(p3));
                o_acc[nt][0] *= a0; o_acc[nt][1] *= a0;
                o_acc[nt][2] *= a1; o_acc[nt][3] *= a1;
            }
            rl0 += __shfl_xor_sync(0xffffffffu, rl0, 1);
            rl0 += __shfl_xor_sync(0xffffffffu, rl0, 2);
            rl1 += __shfl_xor_sync(0xffffffffu, rl1, 1);
            rl1 += __shfl_xor_sync(0xffffffffu, rl1, 2);
            l0 = l0 * a0 + rl0;
            l1 = l1 * a1 + rl1;
            m0 = mn0; m1 = mn1;

            __syncwarp();

            #pragma unroll
            for (int ks = 0; ks < 8; ks++) {
                int pc = ks * 8 + q;
                uint32_t a[4];
                a[0] = Ps[(wr + g) * FST + pc];
                a[1] = Ps[(wr + g + 8) * FST + pc];
                a[2] = Ps[(wr + g) * FST + pc + 4];
                a[3] = Ps[(wr + g + 8) * FST + pc + 4];
                #pragma unroll
                for (int nt = 0; nt < 8; nt++) {
                    uint32_t bv[2];
                    bv[0] = Vs[(ks * 8 + q) * VST + nt * 8 + g];
                    bv[1] = Vs[(ks * 8 + q + 4) * VST + nt * 8 + g];
                    mma_tf32(o_acc[nt], a, bv);
                }
            }
        }
        __syncthreads();
    }

    float inv0 = 1.f / l0, inv1 = 1.f / l1;
    __half* yp0 = y + (size_t)(b * T_SEQ + rg0) * 1024 + h * 64;
    __half* yp1 = yp0 + (size_t)8 * 1024;
    #pragma unroll
    for (int nt = 0; nt < 8; nt++) {
        int c = nt * 8 + 2 * q;
        *(uint32_t*)(yp0 + c) = h2pack(o_acc[nt][0] * inv0, o_acc[nt][1] * inv0);
        *(uint32_t*)(yp1 + c) = h2pack(o_acc[nt][2] * inv1, o_acc[nt][3] * inv1);
    }
}

// ---------------- launch ----------------------------------------------------
#define FLASH_SMEM ((2 * BQ * QST + 2 * BK * QST + BQ * FST + BK * VST) * 4)

extern "C" void kernel_launch(void* const* d_in, const int* in_sizes, int n_in,
                              void* d_out, int out_size) {
    const float* x    = (const float*)d_in[0];
    const int*   ym   = (const int*)  d_in[1];
    const float* Wqkv = (const float*)d_in[2];
    const float* Wap  = (const float*)d_in[3];
    const float* sc1  = (const float*)d_in[4];
    const float* sc2  = (const float*)d_in[5];
    const float* Wfc1 = (const float*)d_in[6];
    const float* Wfc2 = (const float*)d_in[7];
    const float* Wmp  = (const float*)d_in[8];
    float* out = (float*)d_out;

    float *qkv, *x2, *fc1, *fc2;
    float2* ropet;
    __half *h, *y, *m, *wqkvT, *wapT, *wfc1T, *wfc2T, *wmpT;
    cudaGetSymbolAddress((void**)&qkv,   g_qkv);
    cudaGetSymbolAddress((void**)&x2,    g_x2);
    cudaGetSymbolAddress((void**)&fc1,   g_fc1);
    cudaGetSymbolAddress((void**)&fc2,   g_fc2);
    cudaGetSymbolAddress((void**)&h,     g_h);
    cudaGetSymbolAddress((void**)&y,     g_y);
    cudaGetSymbolAddress((void**)&m,     g_m);
    cudaGetSymbolAddress((void**)&wqkvT, g_wqkvT);
    cudaGetSymbolAddress((void**)&wapT,  g_wapT);
    cudaGetSymbolAddress((void**)&wfc1T, g_wfc1T);
    cudaGetSymbolAddress((void**)&wfc2T, g_wfc2T);
    cudaGetSymbolAddress((void**)&wmpT,  g_wmpT);
    cudaGetSymbolAddress((void**)&ropet, g_rope);

    cudaFuncSetAttribute(flash_mma_k,
                         cudaFuncAttributeMaxDynamicSharedMemorySize,
                         FLASH_SMEM);

    dim3 tb(32, 8);
    // 0) weight transpose + fp16 convert; rope table
    tconv_k<<<dim3(3072 / 32, 1024 / 32), tb>>>(Wqkv, wqkvT, C_EMB, 3072);
    tconv_k<<<dim3(1024 / 32, 1024 / 32), tb>>>(Wap, wapT, C_EMB, C_EMB);
    tconv_k<<<dim3(2816 / 32, 1024 / 32), tb>>>(Wfc1, wfc1T, C_EMB, HID);
    tconv_k<<<dim3(2816 / 32, 1024 / 32), tb>>>(Wfc2, wfc2T, C_EMB, HID);
    tconv_k<<<dim3(1024 / 32, 2816 / 32), tb>>>(Wmp, wmpT, HID, C_EMB);
    rope_tab_k<<<(T_SEQ * 32) / 256, 256>>>(ropet);

    // 1) h = fp16(rmsnorm(x, scale1))
    rmsnorm_k<<<TOK, 256>>>(x, sc1, h);
    // 2) qkv = h @ Wqkv
    h16gemm_k<<<dim3(3072 / 128, TOK / 128), 256>>>(
        h, wqkvT, qkv, nullptr, nullptr, nullptr, TOK, 3072, C_EMB);
    // 3) RoPE in place (table-based)
    rope_k<<<(1 << 21) / 256, 256>>>(qkv, ropet);
    // 4) attention -> y (fp16)
    flash_mma_k<<<dim3(T_SEQ / BQ, NHEAD, 2), 256, FLASH_SMEM>>>(qkv, ym, y);
    // 5) x2 = x + y @ Wattn_proj
    h16gemm_k<<<dim3(C_EMB / 128, TOK / 128), 256>>>(
        y, wapT, x2, x, nullptr, nullptr, TOK, C_EMB, C_EMB);
    // 6) h = fp16(rmsnorm(x2, scale2))
    rmsnorm_k<<<TOK, 256>>>(x2, sc2, h);
    // 7) fc1 = h @ Wfc1 (float); then fused fc2 GEMM + silu gate -> m (fp16)
    h16gemm_k<<<dim3(HID / 128, TOK / 128), 256>>>(
        h, wfc1T, fc1, nullptr, nullptr, nullptr, TOK, HID, C_EMB);
    h16gemm_k<<<dim3(HID / 128, TOK / 128), 256>>>(
        h, wfc2T, fc2, nullptr, fc1, m, TOK, HID, C_EMB);
    // 8) out = x2 + m @ Wmlp_proj
    h16gemm_k<<<dim3(C_EMB / 128, TOK / 128), 256>>>(
        m, wmpT, out, x2, nullptr, nullptr, TOK, C_EMB, HID);
}

// round 16
// speedup vs baseline: 1.7621x; 1.1297x over previous
#include <cuda_runtime.h>
#include <cuda_fp16.h>
#include <cstdint>

// Problem constants
#define TOK   4096      // B*T
#define T_SEQ 2048
#define C_EMB 1024
#define NHEAD 16
#define HD    64
#define HID   2816

// ---------------- scratch (static device globals; no allocations) ----------
__device__ __align__(16) float g_qkv[(size_t)TOK * 3 * C_EMB];
__device__ __align__(16) float g_x2 [(size_t)TOK * C_EMB];
__device__ __align__(16) float g_fc1[(size_t)TOK * HID];
__device__ __align__(16) float g_fc2[(size_t)TOK * HID];   // unused in gate mode
// fp16 activations (GEMM A operands)
__device__ __align__(16) __half g_h [(size_t)TOK * C_EMB];
__device__ __align__(16) __half g_y [(size_t)TOK * C_EMB];
__device__ __align__(16) __half g_m [(size_t)TOK * HID];
// transposed fp16 weights [N][K]
__device__ __align__(16) __half g_wqkvT[(size_t)3 * C_EMB * C_EMB];
__device__ __align__(16) __half g_wapT [(size_t)C_EMB * C_EMB];
__device__ __align__(16) __half g_wfc1T[(size_t)HID * C_EMB];
__device__ __align__(16) __half g_wfc2T[(size_t)HID * C_EMB];
__device__ __align__(16) __half g_wmpT [(size_t)C_EMB * HID];
// rope cos/sin table [T_SEQ][32]
__device__ __align__(16) float2 g_rope[(size_t)T_SEQ * 32];

// ---------------- helpers ---------------------------------------------------
__device__ __forceinline__ uint32_t f2tf(float f) {
    uint32_t u;
    asm("cvt.rna.tf32.f32 %0, %1;" : "=r"(u) : "f"(f));
    return u;
}

__device__ __forceinline__ void mma_tf32(float* d, const uint32_t* a,
                                         const uint32_t* b) {
    asm volatile(
        "mma.sync.aligned.m16n8k8.row.col.f32.tf32.tf32.f32 "
        "{%0,%1,%2,%3}, {%4,%5,%6,%7}, {%8,%9}, {%0,%1,%2,%3};\n"
        : "+f"(d[0]), "+f"(d[1]), "+f"(d[2]), "+f"(d[3])
        : "r"(a[0]), "r"(a[1]), "r"(a[2]), "r"(a[3]), "r"(b[0]), "r"(b[1]));
}

__device__ __forceinline__ void mma_f16(float* d, const uint32_t* a,
                                        const uint32_t* b) {
    asm volatile(
        "mma.sync.aligned.m16n8k16.row.col.f32.f16.f16.f32 "
        "{%0,%1,%2,%3}, {%4,%5,%6,%7}, {%8,%9}, {%0,%1,%2,%3};\n"
        : "+f"(d[0]), "+f"(d[1]), "+f"(d[2]), "+f"(d[3])
        : "r"(a[0]), "r"(a[1]), "r"(a[2]), "r"(a[3]), "r"(b[0]), "r"(b[1]));
}

__device__ __forceinline__ void cp_async16(void* smem, const void* gmem) {
    uint32_t s = (uint32_t)__cvta_generic_to_shared(smem);
    asm volatile("cp.async.ca.shared.global [%0], [%1], 16;\n"
                 :: "r"(s), "l"(gmem));
}

__device__ __forceinline__ uint32_t h2pack(float a, float b) {
    __half2 h = __floats2half2_rn(a, b);
    return *(uint32_t*)&h;
}

__device__ __forceinline__ void hsplit2(float a, float b,
                                        uint32_t& hi, uint32_t& lo) {
    __half ha = __float2half_rn(a), hb = __float2half_rn(b);
    __half la = __float2half_rn(a - __half2float(ha));
    __half lb = __float2half_rn(b - __half2float(hb));
    hi = (uint32_t)__half_as_ushort(ha) | ((uint32_t)__half_as_ushort(hb) << 16);
    lo = (uint32_t)__half_as_ushort(la) | ((uint32_t)__half_as_ushort(lb) << 16);
}

// ---------------- weight transpose + fp16 convert ---------------------------
__global__ __launch_bounds__(256) void tconv_k(const float* __restrict__ W,
                                               __half* __restrict__ T,
                                               int K, int N) {
    __shared__ float t[32][33];
    int tx = threadIdx.x, ty = threadIdx.y;
    int n0 = blockIdx.x * 32, k0 = blockIdx.y * 32;
    #pragma unroll
    for (int i = 0; i < 4; i++) {
        int kk = ty * 4 + i;
        t[kk][tx] = W[(size_t)(k0 + kk) * N + n0 + tx];
    }
    __syncthreads();
    #pragma unroll
    for (int i = 0; i < 4; i++) {
        int nn = ty * 4 + i;
        T[(size_t)(n0 + nn) * K + k0 + tx] = __float2half(t[tx][nn]);
    }
}

// ---------------- RMSNorm -> fp16 output ------------------------------------
__global__ __launch_bounds__(256) void rmsnorm_k(const float* __restrict__ x,
                                                 const float* __restrict__ sc,
                                                 __half* __restrict__ out) {
    int row = blockIdx.x;
    const float4* xr = (const float4*)(x + (size_t)row * C_EMB);
    float4 v = xr[threadIdx.x];
    float ss = v.x * v.x + v.y * v.y + v.z * v.z + v.w * v.w;
    #pragma unroll
    for (int o = 16; o; o >>= 1) ss += __shfl_xor_sync(0xffffffffu, ss, o);
    __shared__ float red[8];
    int wid = threadIdx.x >> 5, lane = threadIdx.x & 31;
    if (lane == 0) red[wid] = ss;
    __syncthreads();
    if (wid == 0) {
        float t = (lane < 8) ? red[lane] : 0.f;
        #pragma unroll
        for (int o = 4; o; o >>= 1) t += __shfl_xor_sync(0xffffffffu, t, o);
        if (lane == 0) red[0] = t;
    }
    __syncthreads();
    float inv = rsqrtf(red[0] * (1.0f / C_EMB) + 1e-5f);
    float4 s4 = ((const float4*)sc)[threadIdx.x];
    uint2 o4;
    o4.x = h2pack(v.x * inv * s4.x, v.y * inv * s4.y);
    o4.y = h2pack(v.z * inv * s4.z, v.w * inv * s4.w);
    ((uint2*)(out + (size_t)row * C_EMB))[threadIdx.x] = o4;
}

// ---------------- fp16 tensor-core GEMM: K-tile 64, 2-stage -----------------
// C[M,N] = A[M,K] @ B[N,K]^T (+R). If gate: hout = fp16(silu(gate)*acc).
#define HST 36   // 32-bit words per smem row (64 fp16 = 32 words + 4 pad)
#define GEMM_SMEM (4 * 128 * HST * 4)   // 2 stages x (A+B) = 73728 B

__global__ __launch_bounds__(256) void h16gemm_k(const __half* __restrict__ A,
                                                 const __half* __restrict__ B,
                                                 float* __restrict__ C,
                                                 const float* __restrict__ R,
                                                 const float* __restrict__ gate,
                                                 __half* __restrict__ hout,
                                                 int M, int N, int K) {
    extern __shared__ uint32_t gsm[];
    // layout: [A0][A1][B0][B1], each 128*HST words
    int tid  = threadIdx.x;
    int wid  = tid >> 5;
    int lane = tid & 31;
    int g = lane >> 2;
    int q = lane & 3;
    int wm = (wid >> 2) * 64;
    int wn = (wid & 3) * 32;
    int bx = blockIdx.x * 128;
    int by = blockIdx.y * 128;

    int l_row = tid >> 3;          // 0..31 (4 passes cover 128 rows)
    int l_c   = tid & 7;           // 16B chunk within 128B row

    const __half* Agp = A + (size_t)(by + l_row) * K + l_c * 8;
    const __half* Bgp = B + (size_t)(bx + l_row) * K + l_c * 8;

    float acc[4][4][4];
    #pragma unroll
    for (int i = 0; i < 4; i++)
        #pragma unroll
        for (int j = 0; j < 4; j++)
            #pragma unroll
            for (int e = 0; e < 4; e++) acc[i][j][e] = 0.f;

    auto load_stage = [&](int buf, int k0) {
        uint32_t* Ab = gsm + buf * 128 * HST;
        uint32_t* Bb = gsm + (2 + buf) * 128 * HST;
        #pragma unroll
        for (int i = 0; i < 4; i++) {
            int row = l_row + i * 32;
            cp_async16(&Ab[row * HST + l_c * 4],
                       Agp + (size_t)i * 32 * K + k0);
            cp_async16(&Bb[row * HST + l_c * 4],
                       Bgp + (size_t)i * 32 * K + k0);
        }
        asm volatile("cp.async.commit_group;\n");
    };

    load_stage(0, 0);
    asm volatile("cp.async.wait_group 0;\n");
    __syncthreads();

    int KT = K >> 6;
    for (int kt = 0; kt < KT; kt++) {
        int buf = kt & 1;
        if (kt + 1 < KT) load_stage(buf ^ 1, (kt + 1) << 6);

        const uint32_t* Ab = gsm + buf * 128 * HST;
        const uint32_t* Bb = gsm + (2 + buf) * 128 * HST;
        #pragma unroll
        for (int ks = 0; ks < 4; ks++) {
            uint32_t af[4][4], bf[4][2];
            #pragma unroll
            for (int mt = 0; mt < 4; mt++) {
                int base = (wm + 16 * mt + g) * HST + ks * 8 + q;
                af[mt][0] = Ab[base];
                af[mt][1] = Ab[base + 8 * HST];
                af[mt][2] = Ab[base + 4];
                af[mt][3] = Ab[base + 8 * HST + 4];
            }
            #pragma unroll
            for (int nt = 0; nt < 4; nt++) {
                int base = (wn + 8 * nt + g) * HST + ks * 8 + q;
                bf[nt][0] = Bb[base];
                bf[nt][1] = Bb[base + 4];
            }
            #pragma unroll
            for (int mt = 0; mt < 4; mt++)
                #pragma unroll
                for (int nt = 0; nt < 4; nt++)
                    mma_f16(acc[mt][nt], af[mt], bf[nt]);
        }

        asm volatile("cp.async.wait_group 0;\n");
        __syncthreads();
    }

    if (gate) {
        #pragma unroll
        for (int mt = 0; mt < 4; mt++) {
            #pragma unroll
            for (int nt = 0; nt < 4; nt++) {
                int r0 = by + wm + 16 * mt + g;
                int c0 = bx + wn + 8 * nt + 2 * q;
                float2 g0 = *(const float2*)(gate + (size_t)r0 * N + c0);
                float2 g1 = *(const float2*)(gate + (size_t)(r0 + 8) * N + c0);
                float v00 = g0.x * acc[mt][nt][0] / (1.f + __expf(-g0.x));
                float v01 = g0.y * acc[mt][nt][1] / (1.f + __expf(-g0.y));
                float v10 = g1.x * acc[mt][nt][2] / (1.f + __expf(-g1.x));
                float v11 = g1.y * acc[mt][nt][3] / (1.f + __expf(-g1.y));
                *(uint32_t*)(hout + (size_t)r0 * N + c0)       = h2pack(v00, v01);
                *(uint32_t*)(hout + (size_t)(r0 + 8) * N + c0) = h2pack(v10, v11);
            }
        }
        return;
    }

    #pragma unroll
    for (int mt = 0; mt < 4; mt++) {
        #pragma unroll
        for (int nt = 0; nt < 4; nt++) {
            int r0 = by + wm + 16 * mt + g;
            int c0 = bx + wn + 8 * nt + 2 * q;
            float2 v0 = make_float2(acc[mt][nt][0], acc[mt][nt][1]);
            float2 v1 = make_float2(acc[mt][nt][2], acc[mt][nt][3]);
            if (R) {
                float2 r0v = *(const float2*)(R + (size_t)r0 * N + c0);
                float2 r1v = *(const float2*)(R + (size_t)(r0 + 8) * N + c0);
                v0.x += r0v.x; v0.y += r0v.y;
                v1.x += r1v.x; v1.y += r1v.y;
            }
            *(float2*)(C + (size_t)r0 * N + c0) = v0;
            *(float2*)(C + (size_t)(r0 + 8) * N + c0) = v1;
        }
    }
}

// ---------------- rope table build ------------------------------------------
__global__ __launch_bounds__(256) void rope_tab_k(float2* __restrict__ tab) {
    int idx = blockIdx.x * 256 + threadIdx.x;   // 2048*32
    int t = idx >> 5;
    int p = idx & 31;
    float ang = (float)t * powf(10000.0f, -(float)p / 32.0f);
    tab[idx] = make_float2(cosf(ang), sinf(ang));
}

// ---------------- RoPE: table-based -----------------------------------------
__global__ __launch_bounds__(256) void rope_k(float* __restrict__ qkv,
                                              const float2* __restrict__ tab) {
    int idx = blockIdx.x * 256 + threadIdx.x;   // 2^21 threads
    int j     = idx & 15;
    int h     = (idx >> 4) & 15;
    int which = (idx >> 8) & 1;
    int tok   = idx >> 9;
    int t     = tok & 2047;
    size_t off = (size_t)tok * 3072 + (size_t)which * 1024 + h * 64 + j * 4;
    float4 v = *(float4*)(qkv + off);
    float2 cs0 = tab[t * 32 + 2 * j];
    float2 cs1 = tab[t * 32 + 2 * j + 1];
    float4 o;
    o.x = v.x * cs0.x - v.y * cs0.y;
    o.y = v.x * cs0.y + v.y * cs0.x;
    o.z = v.z * cs1.x - v.w * cs1.y;
    o.w = v.z * cs1.y + v.w * cs1.x;
    *(float4*)(qkv + off) = o;
}

// ---------------- Flash attention: fp16 QK^T (2-term), tf32 PV --------------
#define QST 36
#define FST 68
#define VST 72
#define BQ 128
#define BK 64

__global__ __launch_bounds__(256, 2)
void flash_mma_k(const float* __restrict__ qkv,
                 const int* __restrict__ ymask,
                 __half* __restrict__ y) {
    extern __shared__ uint32_t dyn[];
    uint32_t* Qh = dyn;
    uint32_t* Ql = Qh + BQ * QST;
    uint32_t* Kh = Ql + BQ * QST;
    uint32_t* Kl = Kh + BK * QST;
    uint32_t* Ps = Kl + BK * QST;
    uint32_t* Vs = Ps + BQ * FST;
    __shared__ int yms[64];

    int tid = threadIdx.x;
    int w = tid >> 5, lane = tid & 31;
    int g = lane >> 2, q = lane & 3;
    int qt = gridDim.x - 1 - blockIdx.x;
    int h = blockIdx.y, b = blockIdx.z;
    int q0 = qt * BQ;
    const float* base = qkv + (size_t)(b * T_SEQ) * 3072 + h * 64;

    #pragma unroll
    for (int i = 0; i < 8; i++) {
        int e = tid + i * 256;
        int r = e >> 4;
        int c = (e & 15) * 4;
        float4 v = *(const float4*)(base + (size_t)(q0 + r) * 3072 + c);
        uint2 hv, lv;
        hsplit2(v.x, v.y, hv.x, lv.x);
        hsplit2(v.z, v.w, hv.y, lv.y);
        int o = r * QST + (c >> 1);
        *(uint2*)&Qh[o] = hv;
        *(uint2*)&Ql[o] = lv;
    }
    if (tid < 64) yms[tid] = ymask[b * 64 + tid];
    __syncthreads();

    int wr = w * 16;
    float o_acc[8][4];
    #pragma unroll
    for (int nt = 0; nt < 8; nt++)
        #pragma unroll
        for (int e = 0; e < 4; e++) o_acc[nt][e] = 0.f;
    float m0 = -1e30f, m1 = -1e30f, l0 = 0.f, l1 = 0.f;

    int rg0 = q0 + wr + g, rg1 = rg0 + 8;
    int nkt = 2 * qt + 2;

    for (int kt = 0; kt < nkt; kt++) {
        int k0 = kt * BK;
        #pragma unroll
        for (int i = 0; i < 4; i++) {
            int e = tid + i * 256;
            int r = e >> 4;
            int c = (e & 15) * 4;
            const float* gsrc = base + (size_t)(k0 + r) * 3072 + c;
            float4 kv4 = *(const float4*)(gsrc + 1024);
            float4 vv4 = *(const float4*)(gsrc + 2048);
            uint2 hv, lv;
            hsplit2(kv4.x, kv4.y, hv.x, lv.x);
            hsplit2(kv4.z, kv4.w, hv.y, lv.y);
            int ok = r * QST + (c >> 1);
            *(uint2*)&Kh[ok] = hv;
            *(uint2*)&Kl[ok] = lv;
            int ov = r * VST + c;
            Vs[ov]     = f2tf(vv4.x);
            Vs[ov + 1] = f2tf(vv4.y);
            Vs[ov + 2] = f2tf(vv4.z);
            Vs[ov + 3] = f2tf(vv4.w);
        }
        __syncthreads();

        bool active = (k0 <= q0 + wr + 15);
        if (active) {
            float s[8][4];
            #pragma unroll
            for (int nt = 0; nt < 8; nt++)
                #pragma unroll
                for (int e = 0; e < 4; e++) s[nt][e] = 0.f;

            #pragma unroll
            for (int ks = 0; ks < 4; ks++) {
                int ac = ks * 8 + q;
                uint32_t ah[4], al[4];
                ah[0] = Qh[(wr + g) * QST + ac];
                ah[1] = Qh[(wr + g + 8) * QST + ac];
                ah[2] = Qh[(wr + g) * QST + ac + 4];
                ah[3] = Qh[(wr + g + 8) * QST + ac + 4];
                al[0] = Ql[(wr + g) * QST + ac];
                al[1] = Ql[(wr + g + 8) * QST + ac];
                al[2] = Ql[(wr + g) * QST + ac + 4];
                al[3] = Ql[(wr + g + 8) * QST + ac + 4];
                #pragma unroll
                for (int nt = 0; nt < 8; nt++) {
                    int br = (nt * 8 + g) * QST + ac;
                    uint32_t bh[2] = {Kh[br], Kh[br + 4]};
                    uint32_t bl[2] = {Kl[br], Kl[br + 4]};
                    mma_f16(s[nt], ah, bh);
                    mma_f16(s[nt], al, bh);
                    mma_f16(s[nt], ah, bl);
                }
            }

            bool needmask = (k0 + BK - 1 > q0 + wr);
            bool istext = (q0 == 0) && (k0 == 0);
            float rm0 = -1e30f, rm1 = -1e30f;
            #pragma unroll
            for (int nt = 0; nt < 8; nt++) {
                #pragma unroll
                for (int e = 0; e < 4; e++) {
                    float sv = s[nt][e] * 0.125f;
                    if (needmask) {
                        int row = (e >= 2) ? rg1 : rg0;
                        int kg = k0 + nt * 8 + 2 * q + (e & 1);
                        bool ok = (kg <= row);
                        if (istext)
                            ok = ok || (row < 64 && kg < 64 && yms[row] && yms[kg]);
                        sv = ok ? sv : -1e30f;
                    }
                    s[nt][e] = sv;
                    if (e < 2) rm0 = fmaxf(rm0, sv);
                    else       rm1 = fmaxf(rm1, sv);
                }
            }
            rm0 = fmaxf(rm0, __shfl_xor_sync(0xffffffffu, rm0, 1));
            rm0 = fmaxf(rm0, __shfl_xor_sync(0xffffffffu, rm0, 2));
            rm1 = fmaxf(rm1, __shfl_xor_sync(0xffffffffu, rm1, 1));
            rm1 = fmaxf(rm1, __shfl_xor_sync(0xffffffffu, rm1, 2));

            float mn0 = fmaxf(m0, rm0), mn1 = fmaxf(m1, rm1);
            float a0 = __expf(m0 - mn0), a1 = __expf(m1 - mn1);
            float rl0 = 0.f, rl1 = 0.f;
            #pragma unroll
            for (int nt = 0; nt < 8; nt++) {
                float p0 = __expf(s[nt][0] - mn0);
                float p1 = __expf(s[nt][1] - mn0);
                float p2 = __expf(s[nt][2] - mn1);
                float p3 = __expf(s[nt][3] - mn1);
                rl0 += p0 + p1;
                rl1 += p2 + p3;
                int pc = nt * 8 + 2 * q;
                *(uint2*)&Ps[(wr + g) * FST + pc]     = make_uint2(f2tf(p0), f2tf(p1));
                *(uint2*)&Ps[(wr + g + 8) * FST + pc] = make_uint2(f2tf(p2), f2tf(p3));
                o_acc[nt][0] *= a0; o_acc[nt][1] *= a0;
                o_acc[nt][2] *= a1; o_acc[nt][3] *= a1;
            }
            rl0 += __shfl_xor_sync(0xffffffffu, rl0, 1);
            rl0 += __shfl_xor_sync(0xffffffffu, rl0, 2);
            rl1 += __shfl_xor_sync(0xffffffffu, rl1, 1);
            rl1 += __shfl_xor_sync(0xffffffffu, rl1, 2);
            l0 = l0 * a0 + rl0;
            l1 = l1 * a1 + rl1;
            m0 = mn0; m1 = mn1;

            __syncwarp();

            #pragma unroll
            for (int ks = 0; ks < 8; ks++) {
                int pc = ks * 8 + q;
                uint32_t a[4];
                a[0] = Ps[(wr + g) * FST + pc];
                a[1] = Ps[(wr + g + 8) * FST + pc];
                a[2] = Ps[(wr + g) * FST + pc + 4];
                a[3] = Ps[(wr + g + 8) * FST + pc + 4];
                #pragma unroll
                for (int nt = 0; nt < 8; nt++) {
                    uint32_t bv[2];
                    bv[0] = Vs[(ks * 8 + q) * VST + nt * 8 + g];
                    bv[1] = Vs[(ks * 8 + q + 4) * VST + nt * 8 + g];
                    mma_tf32(o_acc[nt], a, bv);
                }
            }
        }
        __syncthreads();
    }

    float inv0 = 1.f / l0, inv1 = 1.f / l1;
    __half* yp0 = y + (size_t)(b * T_SEQ + rg0) * 1024 + h * 64;
    __half* yp1 = yp0 + (size_t)8 * 1024;
    #pragma unroll
    for (int nt = 0; nt < 8; nt++) {
        int c = nt * 8 + 2 * q;
        *(uint32_t*)(yp0 + c) = h2pack(o_acc[nt][0] * inv0, o_acc[nt][1] * inv0);
        *(uint32_t*)(yp1 + c) = h2pack(o_acc[nt][2] * inv1, o_acc[nt][3] * inv1);
    }
}

// ---------------- launch ----------------------------------------------------
#define FLASH_SMEM ((2 * BQ * QST + 2 * BK * QST + BQ * FST + BK * VST) * 4)

extern "C" void kernel_launch(void* const* d_in, const int* in_sizes, int n_in,
                              void* d_out, int out_size) {
    const float* x    = (const float*)d_in[0];
    const int*   ym   = (const int*)  d_in[1];
    const float* Wqkv = (const float*)d_in[2];
    const float* Wap  = (const float*)d_in[3];
    const float* sc1  = (const float*)d_in[4];
    const float* sc2  = (const float*)d_in[5];
    const float* Wfc1 = (const float*)d_in[6];
    const float* Wfc2 = (const float*)d_in[7];
    const float* Wmp  = (const float*)d_in[8];
    float* out = (float*)d_out;

    float *qkv, *x2, *fc1, *fc2;
    float2* ropet;
    __half *h, *y, *m, *wqkvT, *wapT, *wfc1T, *wfc2T, *wmpT;
    cudaGetSymbolAddress((void**)&qkv,   g_qkv);
    cudaGetSymbolAddress((void**)&x2,    g_x2);
    cudaGetSymbolAddress((void**)&fc1,   g_fc1);
    cudaGetSymbolAddress((void**)&fc2,   g_fc2);
    cudaGetSymbolAddress((void**)&h,     g_h);
    cudaGetSymbolAddress((void**)&y,     g_y);
    cudaGetSymbolAddress((void**)&m,     g_m);
    cudaGetSymbolAddress((void**)&wqkvT, g_wqkvT);
    cudaGetSymbolAddress((void**)&wapT,  g_wapT);
    cudaGetSymbolAddress((void**)&wfc1T, g_wfc1T);
    cudaGetSymbolAddress((void**)&wfc2T, g_wfc2T);
    cudaGetSymbolAddress((void**)&wmpT,  g_wmpT);
    cudaGetSymbolAddress((void**)&ropet, g_rope);

    cudaFuncSetAttribute(flash_mma_k,
                         cudaFuncAttributeMaxDynamicSharedMemorySize,
                         FLASH_SMEM);
    cudaFuncSetAttribute(h16gemm_k,
                         cudaFuncAttributeMaxDynamicSharedMemorySize,
                         GEMM_SMEM);

    dim3 tb(32, 8);
    // 0) weight transpose + fp16 convert; rope table
    tconv_k<<<dim3(3072 / 32, 1024 / 32), tb>>>(Wqkv, wqkvT, C_EMB, 3072);
    tconv_k<<<dim3(1024 / 32, 1024 / 32), tb>>>(Wap, wapT, C_EMB, C_EMB);
    tconv_k<<<dim3(2816 / 32, 1024 / 32), tb>>>(Wfc1, wfc1T, C_EMB, HID);
    tconv_k<<<dim3(2816 / 32, 1024 / 32), tb>>>(Wfc2, wfc2T, C_EMB, HID);
    tconv_k<<<dim3(1024 / 32, 2816 / 32), tb>>>(Wmp, wmpT, HID, C_EMB);
    rope_tab_k<<<(T_SEQ * 32) / 256, 256>>>(ropet);

    // 1) h = fp16(rmsnorm(x, scale1))
    rmsnorm_k<<<TOK, 256>>>(x, sc1, h);
    // 2) qkv = h @ Wqkv
    h16gemm_k<<<dim3(3072 / 128, TOK / 128), 256, GEMM_SMEM>>>(
        h, wqkvT, qkv, nullptr, nullptr, nullptr, TOK, 3072, C_EMB);
    // 3) RoPE in place (table-based)
    rope_k<<<(1 << 21) / 256, 256>>>(qkv, ropet);
    // 4) attention -> y (fp16)
    flash_mma_k<<<dim3(T_SEQ / BQ, NHEAD, 2), 256, FLASH_SMEM>>>(qkv, ym, y);
    // 5) x2 = x + y @ Wattn_proj
    h16gemm_k<<<dim3(C_EMB / 128, TOK / 128), 256, GEMM_SMEM>>>(
        y, wapT, x2, x, nullptr, nullptr, TOK, C_EMB, C_EMB);
    // 6) h = fp16(rmsnorm(x2, scale2))
    rmsnorm_k<<<TOK, 256>>>(x2, sc2, h);
    // 7) fc1 = h @ Wfc1; fused fc2 GEMM + silu gate -> m (fp16)
    h16gemm_k<<<dim3(HID / 128, TOK / 128), 256, GEMM_SMEM>>>(
        h, wfc1T, fc1, nullptr, nullptr, nullptr, TOK, HID, C_EMB);
    h16gemm_k<<<dim3(HID / 128, TOK / 128), 256, GEMM_SMEM>>>(
        h, wfc2T, fc2, nullptr, fc1, m, TOK, HID, C_EMB);
    // 8) out = x2 + m @ Wmlp_proj
    h16gemm_k<<<dim3(C_EMB / 128, TOK / 128), 256, GEMM_SMEM>>>(
        m, wmpT, out, x2, nullptr, nullptr, TOK, C_EMB, HID);
}